// round 11
// baseline (speedup 1.0000x reference)
#include <cuda_runtime.h>
#include <math.h>

// Scratch (no cudaMalloc allowed). Zero-initialized at module load;
// g_cnt is self-cleaning (last warp resets to 0) so graph replays see 0.
__device__ float g_rinv[16384];
__device__ float g_part[16384 * 8];
__device__ unsigned int g_cnt[16384];

// ---------------------------------------------------------------------------
// Kernel 1: warp-autonomous row partials + in-kernel finalize.
// One 256-thread block per row; each of 8 warps owns a contiguous 4KB chunk,
// front-batches 8 LDG.128/lane, shuffle-reduces, writes ONE partial, bumps
// the row counter. The LAST warp to finish sums the 8 partials in fixed
// order (deterministic), writes r_inv, resets the counter.
// No smem, no __syncthreads -> pure read stream (82% DRAM in R10).
// ---------------------------------------------------------------------------
__global__ void __launch_bounds__(256) partial_kernel(
    const float* __restrict__ adj, int n)
{
    const int tid  = threadIdx.x;
    const int lane = tid & 31;
    const int warp = tid >> 5;                     // 0..7
    const int row  = blockIdx.x;
    const int n4   = n >> 2;                       // 2048
    const int chunk = n4 >> 3;                     // 256 float4 per warp

    const float4* r4 = reinterpret_cast<const float4*>(adj + (size_t)row * n)
                     + warp * chunk;

    float4 v[8];
    #pragma unroll
    for (int k = 0; k < 8; ++k)
        v[k] = r4[lane + k * 32];

    float4 a0 = make_float4(0.f, 0.f, 0.f, 0.f);
    float4 a1 = make_float4(0.f, 0.f, 0.f, 0.f);
    #pragma unroll
    for (int k = 0; k < 4; ++k) {
        a0.x += v[k].x;   a0.y += v[k].y;   a0.z += v[k].z;   a0.w += v[k].w;
        a1.x += v[k+4].x; a1.y += v[k+4].y; a1.z += v[k+4].z; a1.w += v[k+4].w;
    }
    float s = ((a0.x + a0.y) + (a0.z + a0.w)) + ((a1.x + a1.y) + (a1.z + a1.w));

    #pragma unroll
    for (int off = 16; off > 0; off >>= 1)
        s += __shfl_xor_sync(0xFFFFFFFFu, s, off);

    if (lane == 0) {
        g_part[row * 8 + warp] = s;
        __threadfence();                            // publish partial
        unsigned int prev = atomicAdd(&g_cnt[row], 1u);
        if (prev == 7u) {                           // last warp for this row
            __threadfence();                        // order reads after count
            const float* p = &g_part[row * 8];
            // fixed summation order -> deterministic
            float t = ((p[0] + p[1]) + (p[2] + p[3]))
                    + ((p[4] + p[5]) + (p[6] + p[7]));
            float rs = t + 1.0f;                    // + I diagonal
            g_rinv[row] = (rs > 0.f) ? rsqrtf(rs) : 0.f;
            g_cnt[row] = 0u;                        // self-clean for replay
        }
    }
}

// ---------------------------------------------------------------------------
// Kernel 2: one block per row (mixed r+w DRAM ceiling; frozen for 7 rounds).
// ---------------------------------------------------------------------------
__global__ void __launch_bounds__(256) scale_kernel(
    const float* __restrict__ adj, float* __restrict__ out, int n)
{
    const int row = (n - 1) - blockIdx.x;
    const int tid = threadIdx.x;
    const float ri = g_rinv[row];
    const float4* arow = reinterpret_cast<const float4*>(adj + (size_t)row * n);
    float4* orow = reinterpret_cast<float4*>(out + (size_t)row * n);
    const float4* rinv4 = reinterpret_cast<const float4*>(g_rinv);
    const int n4 = n >> 2;

    #pragma unroll 8
    for (int c = tid; c < n4; c += 256) {
        float4 a = __ldcs(&arow[c]);
        float4 r = rinv4[c];
        int j0 = c << 2;
        a.x += (j0 + 0 == row) ? 1.0f : 0.0f;
        a.y += (j0 + 1 == row) ? 1.0f : 0.0f;
        a.z += (j0 + 2 == row) ? 1.0f : 0.0f;
        a.w += (j0 + 3 == row) ? 1.0f : 0.0f;
        float4 o;
        o.x = a.x * ri * r.x;
        o.y = a.y * ri * r.y;
        o.z = a.z * ri * r.z;
        o.w = a.w * ri * r.w;
        __stcs(&orow[c], o);
    }
}

extern "C" void kernel_launch(void* const* d_in, const int* in_sizes, int n_in,
                              void* d_out, int out_size)
{
    const float* adj = (const float*)d_in[0];
    float* out = (float*)d_out;

    int n = 1;
    {
        long long total = in_sizes[0];
        long long lo = 1, hi = 1 << 16;
        while (lo < hi) {
            long long mid = (lo + hi + 1) >> 1;
            if (mid * mid <= total) lo = mid; else hi = mid - 1;
        }
        n = (int)lo;
    }

    partial_kernel<<<n, 256>>>(adj, n);
    scale_kernel<<<n, 256>>>(adj, out, n);
}

// round 12
// speedup vs baseline: 1.0469x; 1.0469x over previous
#include <cuda_runtime.h>
#include <math.h>

// Scratch (no cudaMalloc allowed).
__device__ float g_rinv[16384];
__device__ float g_part[16384 * 8];   // 8 partials per row

// ---------------------------------------------------------------------------
// Kernel A: warp-autonomous row partials (R10 form, proven 41.9us / 82% DRAM).
// One 256-thread block per row; each of 8 warps owns a contiguous 4KB chunk,
// front-batches 8 LDG.128/lane, shuffle-reduces, writes ONE partial.
// No smem, no __syncthreads, no fences -> pure read stream.
// ---------------------------------------------------------------------------
__global__ void __launch_bounds__(256) partial_kernel(
    const float* __restrict__ adj, int n)
{
    const int tid  = threadIdx.x;
    const int lane = tid & 31;
    const int warp = tid >> 5;                     // 0..7
    const int row  = blockIdx.x;
    const int n4   = n >> 2;                       // 2048
    const int chunk = n4 >> 3;                     // 256 float4 per warp

    const float4* r4 = reinterpret_cast<const float4*>(adj + (size_t)row * n)
                     + warp * chunk;

    float4 v[8];
    #pragma unroll
    for (int k = 0; k < 8; ++k)
        v[k] = r4[lane + k * 32];

    float4 a0 = make_float4(0.f, 0.f, 0.f, 0.f);
    float4 a1 = make_float4(0.f, 0.f, 0.f, 0.f);
    #pragma unroll
    for (int k = 0; k < 4; ++k) {
        a0.x += v[k].x;   a0.y += v[k].y;   a0.z += v[k].z;   a0.w += v[k].w;
        a1.x += v[k+4].x; a1.y += v[k+4].y; a1.z += v[k+4].z; a1.w += v[k+4].w;
    }
    float s = ((a0.x + a0.y) + (a0.z + a0.w)) + ((a1.x + a1.y) + (a1.z + a1.w));

    #pragma unroll
    for (int off = 16; off > 0; off >>= 1)
        s += __shfl_xor_sync(0xFFFFFFFFu, s, off);

    if (lane == 0)
        g_part[row * 8 + warp] = s;

    // release the dependent grid as early as possible
    cudaTriggerProgrammaticLaunchCompletion();
}

// ---------------------------------------------------------------------------
// Kernel B: finalize (PDL). Launches under kernel A's tail; syncs on A's
// completion before reading partials. One thread per row, fixed-order sum.
// ---------------------------------------------------------------------------
__global__ void __launch_bounds__(256) finalize_kernel(int n)
{
    int row = blockIdx.x * blockDim.x + threadIdx.x;
    cudaGridDependencySynchronize();               // wait for partial_kernel
    if (row < n) {
        const float4* p = reinterpret_cast<const float4*>(&g_part[row * 8]);
        float4 a = p[0], b = p[1];
        float t = ((a.x + a.y) + (a.z + a.w)) + ((b.x + b.y) + (b.z + b.w));
        float rs = t + 1.0f;                       // + I diagonal
        g_rinv[row] = (rs > 0.f) ? rsqrtf(rs) : 0.f;
    }
    cudaTriggerProgrammaticLaunchCompletion();
}

// ---------------------------------------------------------------------------
// Kernel C: scale (PDL). Launches under kernel B; syncs before reading
// g_rinv. Inner loop frozen (8 rounds at the mixed r+w DRAM ceiling).
// ---------------------------------------------------------------------------
__global__ void __launch_bounds__(256) scale_kernel(
    const float* __restrict__ adj, float* __restrict__ out, int n)
{
    const int row = (n - 1) - blockIdx.x;
    const int tid = threadIdx.x;
    cudaGridDependencySynchronize();               // wait for finalize_kernel
    const float ri = g_rinv[row];
    const float4* arow = reinterpret_cast<const float4*>(adj + (size_t)row * n);
    float4* orow = reinterpret_cast<float4*>(out + (size_t)row * n);
    const float4* rinv4 = reinterpret_cast<const float4*>(g_rinv);
    const int n4 = n >> 2;

    #pragma unroll 8
    for (int c = tid; c < n4; c += 256) {
        float4 a = __ldcs(&arow[c]);
        float4 r = rinv4[c];
        int j0 = c << 2;
        a.x += (j0 + 0 == row) ? 1.0f : 0.0f;
        a.y += (j0 + 1 == row) ? 1.0f : 0.0f;
        a.z += (j0 + 2 == row) ? 1.0f : 0.0f;
        a.w += (j0 + 3 == row) ? 1.0f : 0.0f;
        float4 o;
        o.x = a.x * ri * r.x;
        o.y = a.y * ri * r.y;
        o.z = a.z * ri * r.z;
        o.w = a.w * ri * r.w;
        __stcs(&orow[c], o);
    }
}

extern "C" void kernel_launch(void* const* d_in, const int* in_sizes, int n_in,
                              void* d_out, int out_size)
{
    const float* adj = (const float*)d_in[0];
    float* out = (float*)d_out;

    int n = 1;
    {
        long long total = in_sizes[0];
        long long lo = 1, hi = 1 << 16;
        while (lo < hi) {
            long long mid = (lo + hi + 1) >> 1;
            if (mid * mid <= total) lo = mid; else hi = mid - 1;
        }
        n = (int)lo;
    }

    // Kernel A: plain launch.
    partial_kernel<<<n, 256>>>(adj, n);

    // Kernels B, C: programmatic dependent launch (overlap launch with
    // predecessor tail; correctness via cudaGridDependencySynchronize()).
    cudaLaunchAttribute attr[1];
    attr[0].id = cudaLaunchAttributeProgrammaticStreamSerialization;
    attr[0].val.programmaticStreamSerializationAllowed = 1;

    cudaLaunchConfig_t cfg = {};
    cfg.blockDim = dim3(256, 1, 1);
    cfg.dynamicSmemBytes = 0;
    cfg.stream = 0;
    cfg.attrs = attr;
    cfg.numAttrs = 1;

    cfg.gridDim = dim3((unsigned)((n + 255) / 256), 1, 1);
    cudaLaunchKernelEx(&cfg, finalize_kernel, n);

    cfg.gridDim = dim3((unsigned)n, 1, 1);
    cudaLaunchKernelEx(&cfg, scale_kernel, adj, out, n);
}

// round 13
// speedup vs baseline: 1.0556x; 1.0084x over previous
#include <cuda_runtime.h>
#include <math.h>

// Scratch (no cudaMalloc allowed).
__device__ float g_rinv[16384];
__device__ float g_part[16384 * 8];   // 8 partials per row

// ---------------------------------------------------------------------------
// Kernel A: warp-autonomous row partials (proven 41.4us / 83% DRAM = LTS cap).
// ---------------------------------------------------------------------------
__global__ void __launch_bounds__(256) partial_kernel(
    const float* __restrict__ adj, int n)
{
    const int tid  = threadIdx.x;
    const int lane = tid & 31;
    const int warp = tid >> 5;                     // 0..7
    const int row  = blockIdx.x;
    const int n4   = n >> 2;                       // 2048
    const int chunk = n4 >> 3;                     // 256 float4 per warp

    const float4* r4 = reinterpret_cast<const float4*>(adj + (size_t)row * n)
                     + warp * chunk;

    float4 v[8];
    #pragma unroll
    for (int k = 0; k < 8; ++k)
        v[k] = r4[lane + k * 32];

    float4 a0 = make_float4(0.f, 0.f, 0.f, 0.f);
    float4 a1 = make_float4(0.f, 0.f, 0.f, 0.f);
    #pragma unroll
    for (int k = 0; k < 4; ++k) {
        a0.x += v[k].x;   a0.y += v[k].y;   a0.z += v[k].z;   a0.w += v[k].w;
        a1.x += v[k+4].x; a1.y += v[k+4].y; a1.z += v[k+4].z; a1.w += v[k+4].w;
    }
    float s = ((a0.x + a0.y) + (a0.z + a0.w)) + ((a1.x + a1.y) + (a1.z + a1.w));

    #pragma unroll
    for (int off = 16; off > 0; off >>= 1)
        s += __shfl_xor_sync(0xFFFFFFFFu, s, off);

    if (lane == 0)
        g_part[row * 8 + warp] = s;

    cudaTriggerProgrammaticLaunchCompletion();
}

// ---------------------------------------------------------------------------
// Kernel B: finalize (PDL). One thread per row, fixed-order sum -> r_inv.
// ---------------------------------------------------------------------------
__global__ void __launch_bounds__(256) finalize_kernel(int n)
{
    int row = blockIdx.x * blockDim.x + threadIdx.x;
    cudaGridDependencySynchronize();               // wait for partial_kernel
    if (row < n) {
        const float4* p = reinterpret_cast<const float4*>(&g_part[row * 8]);
        float4 a = p[0], b = p[1];
        float t = ((a.x + a.y) + (a.z + a.w)) + ((b.x + b.y) + (b.z + b.w));
        float rs = t + 1.0f;                       // + I diagonal
        g_rinv[row] = (rs > 0.f) ? rsqrtf(rs) : 0.f;
    }
    cudaTriggerProgrammaticLaunchCompletion();
}

// ---------------------------------------------------------------------------
// Kernel C: scale (PDL) with PRE-SYNC PREFETCH. The adj reads are independent
// of g_rinv, so the first 4 float4/thread are issued BEFORE the dependency
// sync -> those DRAM reads overlap the predecessor's tail. Multiply happens
// only after sync. Remaining 4 iterations stream as before.
// ---------------------------------------------------------------------------
__global__ void __launch_bounds__(256) scale_kernel(
    const float* __restrict__ adj, float* __restrict__ out, int n)
{
    const int row = (n - 1) - blockIdx.x;
    const int tid = threadIdx.x;
    const float4* arow = reinterpret_cast<const float4*>(adj + (size_t)row * n);
    float4* orow = reinterpret_cast<float4*>(out + (size_t)row * n);
    const float4* rinv4 = reinterpret_cast<const float4*>(g_rinv);
    const int n4 = n >> 2;                         // 2048

    // --- prefetch first half of this thread's columns (independent of rinv) ---
    float4 pf[4];
    #pragma unroll
    for (int k = 0; k < 4; ++k) {
        int c = tid + k * 256;
        pf[k] = __ldcs(&arow[c]);
    }

    cudaGridDependencySynchronize();               // now wait for r_inv
    const float ri = g_rinv[row];

    // --- consume prefetched half ---
    #pragma unroll
    for (int k = 0; k < 4; ++k) {
        int c = tid + k * 256;
        float4 a = pf[k];
        float4 r = rinv4[c];
        int j0 = c << 2;
        a.x += (j0 + 0 == row) ? 1.0f : 0.0f;
        a.y += (j0 + 1 == row) ? 1.0f : 0.0f;
        a.z += (j0 + 2 == row) ? 1.0f : 0.0f;
        a.w += (j0 + 3 == row) ? 1.0f : 0.0f;
        float4 o;
        o.x = a.x * ri * r.x;
        o.y = a.y * ri * r.y;
        o.z = a.z * ri * r.z;
        o.w = a.w * ri * r.w;
        __stcs(&orow[c], o);
    }

    // --- stream the second half ---
    #pragma unroll
    for (int k = 4; k < 8; ++k) {
        int c = tid + k * 256;
        if (c >= n4) break;
        float4 a = __ldcs(&arow[c]);
        float4 r = rinv4[c];
        int j0 = c << 2;
        a.x += (j0 + 0 == row) ? 1.0f : 0.0f;
        a.y += (j0 + 1 == row) ? 1.0f : 0.0f;
        a.z += (j0 + 2 == row) ? 1.0f : 0.0f;
        a.w += (j0 + 3 == row) ? 1.0f : 0.0f;
        float4 o;
        o.x = a.x * ri * r.x;
        o.y = a.y * ri * r.y;
        o.z = a.z * ri * r.z;
        o.w = a.w * ri * r.w;
        __stcs(&orow[c], o);
    }
}

extern "C" void kernel_launch(void* const* d_in, const int* in_sizes, int n_in,
                              void* d_out, int out_size)
{
    const float* adj = (const float*)d_in[0];
    float* out = (float*)d_out;

    int n = 1;
    {
        long long total = in_sizes[0];
        long long lo = 1, hi = 1 << 16;
        while (lo < hi) {
            long long mid = (lo + hi + 1) >> 1;
            if (mid * mid <= total) lo = mid; else hi = mid - 1;
        }
        n = (int)lo;
    }

    partial_kernel<<<n, 256>>>(adj, n);

    cudaLaunchAttribute attr[1];
    attr[0].id = cudaLaunchAttributeProgrammaticStreamSerialization;
    attr[0].val.programmaticStreamSerializationAllowed = 1;

    cudaLaunchConfig_t cfg = {};
    cfg.blockDim = dim3(256, 1, 1);
    cfg.dynamicSmemBytes = 0;
    cfg.stream = 0;
    cfg.attrs = attr;
    cfg.numAttrs = 1;

    cfg.gridDim = dim3((unsigned)((n + 255) / 256), 1, 1);
    cudaLaunchKernelEx(&cfg, finalize_kernel, n);

    cfg.gridDim = dim3((unsigned)n, 1, 1);
    cudaLaunchKernelEx(&cfg, scale_kernel, adj, out, n);
}

// round 14
// speedup vs baseline: 1.0601x; 1.0042x over previous
#include <cuda_runtime.h>
#include <math.h>

// Scratch (no cudaMalloc allowed).
__device__ float g_rinv[16384];
__device__ float g_part[16384 * 8];   // 8 partials per row

// ---------------------------------------------------------------------------
// Kernel A: warp-autonomous row partials. 128-thread blocks (finer wave-tail
// granularity than 256); each block carries 4 global warp-chunks. Per-warp
// work is bit-identical to R13: 8 front-batched LDG.128/lane over a 4KB
// chunk, shuffle reduce, one partial store. No smem, no barriers.
// ---------------------------------------------------------------------------
__global__ void __launch_bounds__(128) partial_kernel(
    const float* __restrict__ adj, int n)
{
    const int tid   = threadIdx.x;
    const int lane  = tid & 31;
    const int warp  = tid >> 5;                    // 0..3
    const int gchunk = blockIdx.x * 4 + warp;      // global chunk id
    const int row   = gchunk >> 3;
    const int chunk = gchunk & 7;
    const int n4    = n >> 2;                      // 2048
    const int csz   = n4 >> 3;                     // 256 float4 per chunk

    const float4* r4 = reinterpret_cast<const float4*>(adj + (size_t)row * n)
                     + chunk * csz;

    float4 v[8];
    #pragma unroll
    for (int k = 0; k < 8; ++k)
        v[k] = r4[lane + k * 32];

    float4 a0 = make_float4(0.f, 0.f, 0.f, 0.f);
    float4 a1 = make_float4(0.f, 0.f, 0.f, 0.f);
    #pragma unroll
    for (int k = 0; k < 4; ++k) {
        a0.x += v[k].x;   a0.y += v[k].y;   a0.z += v[k].z;   a0.w += v[k].w;
        a1.x += v[k+4].x; a1.y += v[k+4].y; a1.z += v[k+4].z; a1.w += v[k+4].w;
    }
    float s = ((a0.x + a0.y) + (a0.z + a0.w)) + ((a1.x + a1.y) + (a1.z + a1.w));

    #pragma unroll
    for (int off = 16; off > 0; off >>= 1)
        s += __shfl_xor_sync(0xFFFFFFFFu, s, off);

    if (lane == 0)
        g_part[row * 8 + chunk] = s;

    cudaTriggerProgrammaticLaunchCompletion();
}

// ---------------------------------------------------------------------------
// Kernel B: finalize (PDL). One thread per row, fixed-order sum -> r_inv.
// ---------------------------------------------------------------------------
__global__ void __launch_bounds__(256) finalize_kernel(int n)
{
    int row = blockIdx.x * blockDim.x + threadIdx.x;
    cudaGridDependencySynchronize();               // wait for partial_kernel
    if (row < n) {
        const float4* p = reinterpret_cast<const float4*>(&g_part[row * 8]);
        float4 a = p[0], b = p[1];
        float t = ((a.x + a.y) + (a.z + a.w)) + ((b.x + b.y) + (b.z + b.w));
        float rs = t + 1.0f;                       // + I diagonal
        g_rinv[row] = (rs > 0.f) ? rsqrtf(rs) : 0.f;
    }
    cudaTriggerProgrammaticLaunchCompletion();
}

// ---------------------------------------------------------------------------
// Kernel C: scale (PDL). Pre-sync: 4-deep register prefetch + zero-register
// L2 prefetch of the second half -> the whole row's DRAM fetch overlaps the
// predecessor tail at no occupancy cost. Inner math frozen (LTS-cap-bound).
// ---------------------------------------------------------------------------
__global__ void __launch_bounds__(256) scale_kernel(
    const float* __restrict__ adj, float* __restrict__ out, int n)
{
    const int row = (n - 1) - blockIdx.x;
    const int tid = threadIdx.x;
    const float4* arow = reinterpret_cast<const float4*>(adj + (size_t)row * n);
    float4* orow = reinterpret_cast<float4*>(out + (size_t)row * n);
    const float4* rinv4 = reinterpret_cast<const float4*>(g_rinv);
    const int n4 = n >> 2;                         // 2048

    // --- pre-sync: register prefetch of first half ---
    float4 pf[4];
    #pragma unroll
    for (int k = 0; k < 4; ++k) {
        int c = tid + k * 256;
        pf[k] = __ldcs(&arow[c]);
    }
    // --- pre-sync: L2 prefetch of second half (no registers consumed) ---
    #pragma unroll
    for (int k = 4; k < 8; ++k) {
        const float4* p = &arow[tid + k * 256];
        asm volatile("prefetch.global.L2 [%0];" :: "l"(p));
    }

    cudaGridDependencySynchronize();               // now wait for r_inv
    const float ri = g_rinv[row];

    // --- consume prefetched half ---
    #pragma unroll
    for (int k = 0; k < 4; ++k) {
        int c = tid + k * 256;
        float4 a = pf[k];
        float4 r = rinv4[c];
        int j0 = c << 2;
        a.x += (j0 + 0 == row) ? 1.0f : 0.0f;
        a.y += (j0 + 1 == row) ? 1.0f : 0.0f;
        a.z += (j0 + 2 == row) ? 1.0f : 0.0f;
        a.w += (j0 + 3 == row) ? 1.0f : 0.0f;
        float4 o;
        o.x = a.x * ri * r.x;
        o.y = a.y * ri * r.y;
        o.z = a.z * ri * r.z;
        o.w = a.w * ri * r.w;
        __stcs(&orow[c], o);
    }

    // --- stream the second half (L2-warmed) ---
    #pragma unroll
    for (int k = 4; k < 8; ++k) {
        int c = tid + k * 256;
        if (c >= n4) break;
        float4 a = __ldcs(&arow[c]);
        float4 r = rinv4[c];
        int j0 = c << 2;
        a.x += (j0 + 0 == row) ? 1.0f : 0.0f;
        a.y += (j0 + 1 == row) ? 1.0f : 0.0f;
        a.z += (j0 + 2 == row) ? 1.0f : 0.0f;
        a.w += (j0 + 3 == row) ? 1.0f : 0.0f;
        float4 o;
        o.x = a.x * ri * r.x;
        o.y = a.y * ri * r.y;
        o.z = a.z * ri * r.z;
        o.w = a.w * ri * r.w;
        __stcs(&orow[c], o);
    }
}

extern "C" void kernel_launch(void* const* d_in, const int* in_sizes, int n_in,
                              void* d_out, int out_size)
{
    const float* adj = (const float*)d_in[0];
    float* out = (float*)d_out;

    int n = 1;
    {
        long long total = in_sizes[0];
        long long lo = 1, hi = 1 << 16;
        while (lo < hi) {
            long long mid = (lo + hi + 1) >> 1;
            if (mid * mid <= total) lo = mid; else hi = mid - 1;
        }
        n = (int)lo;
    }

    partial_kernel<<<n * 2, 128>>>(adj, n);        // 2n blocks x 4 chunks = 8n chunks

    cudaLaunchAttribute attr[1];
    attr[0].id = cudaLaunchAttributeProgrammaticStreamSerialization;
    attr[0].val.programmaticStreamSerializationAllowed = 1;

    cudaLaunchConfig_t cfg = {};
    cfg.blockDim = dim3(256, 1, 1);
    cfg.dynamicSmemBytes = 0;
    cfg.stream = 0;
    cfg.attrs = attr;
    cfg.numAttrs = 1;

    cfg.gridDim = dim3((unsigned)((n + 255) / 256), 1, 1);
    cudaLaunchKernelEx(&cfg, finalize_kernel, n);

    cfg.gridDim = dim3((unsigned)n, 1, 1);
    cudaLaunchKernelEx(&cfg, scale_kernel, adj, out, n);
}